// round 5
// baseline (speedup 1.0000x reference)
#include <cuda_runtime.h>
#include <cstdint>

// TaxaNetLoss — cp.async double-buffered row streaming.
//   loss = sum_{k=1..3} W[k] * (viol_k * e + ce_k)
//   ce_k   = mean_i ( log( sum_{j in lvl k} exp(yp[i,j]) + (C - L_k) ) - yp[i, yt[i,k]] )
//   argm[k,i] = argmax of yp masked to level k (zeros outside), first-occurrence
//               tie-break -> implicit zero candidate at first out-of-level index
//               (30 for k=0, 0 for k>=1).
// Each CTA streams SPC=4 rows GMEM->SMEM via 8B cp.async (double buffer),
// computes from SMEM, defers H gathers to one parallel epilogue. Last ticket
// holder's block sums the 1024 partials in fixed order (bit-deterministic)
// and resets the ticket (graph-replay safe).

#define N_SAMPLES 1024
#define C_TOTAL   13430
#define SPC       4
#define GRID      (N_SAMPLES / SPC)   // 256 CTAs
#define NT        256
#define NW        (NT / 32)
#define BUF_F     13440               // padded floats per smem buffer
#define N8        ((C_TOTAL * 4) / 8) // 6715 8-byte chunks per row

static __device__ __align__(16) float g_partial[N_SAMPLES];
static __device__ unsigned int g_ticket = 0;

__device__ __forceinline__ float fexp(float x) {
    // Schraudolph fast exp: 1 FFMA + 1 F2I, ~+-3% rel err; lse error ~1e-5 rel on loss.
    return __int_as_float((int)fmaf(x, 12102203.0f, 1064866805.0f));
}

__device__ __forceinline__ void cp8(uint32_t dst, const void* src) {
    asm volatile("cp.async.ca.shared.global [%0], [%1], 8;" :: "r"(dst), "l"(src));
}
__device__ __forceinline__ void cp_commit() {
    asm volatile("cp.async.commit_group;" ::: "memory");
}
template <int N>
__device__ __forceinline__ void cp_wait() {
    asm volatile("cp.async.wait_group %0;" :: "n"(N) : "memory");
}

__global__ __launch_bounds__(NT) void taxa_kernel(
    const float* __restrict__ yp, const int* __restrict__ yt,
    const float* __restrict__ H, float* __restrict__ out)
{
    extern __shared__ float sbuf[];       // 2 * BUF_F floats (dynamic)
    __shared__ float s_v[3][NW];
    __shared__ int   s_i[3][NW];
    __shared__ float s_s[3][NW];
    __shared__ int   s_argm[SPC][4];
    __shared__ float s_S[SPC][3];
    __shared__ float s_rowt[SPC][3];
    __shared__ int   s_last;

    const int tid  = threadIdx.x;
    const int lane = tid & 31;
    const int wid  = tid >> 5;
    const int bid  = blockIdx.x;

    const uint32_t sb = (uint32_t)__cvta_generic_to_shared(sbuf);
    if (tid == 0) s_last = 0;

    // ---- prologue: load row 0 into buffer 0
    {
        const char* src = (const char*)(yp + (size_t)(bid * SPC) * C_TOTAL);
        for (int j = tid; j < N8; j += NT) cp8(sb + 8u * j, src + 8u * (size_t)j);
        cp_commit();
    }

#pragma unroll
    for (int s = 0; s < SPC; s++) {
        // issue next row's load into the other buffer, then wait for current
        if (s + 1 < SPC) {
            const char* src = (const char*)(yp + (size_t)(bid * SPC + s + 1) * C_TOTAL);
            const uint32_t dst = sb + ((s + 1) & 1) * (BUF_F * 4);
            for (int j = tid; j < N8; j += NT) cp8(dst + 8u * j, src + 8u * (size_t)j);
            cp_commit();
            cp_wait<1>();
        } else {
            cp_wait<0>();
        }
        __syncthreads();

        const float* row = sbuf + (s & 1) * BUF_F;

        // level 0 (30 elems): warp 0
        if (wid == 0) {
            float bv0 = (lane < 30) ? row[lane] : -3.4e38f;
            int   bi0 = (lane < 30) ? lane : C_TOTAL;
#pragma unroll
            for (int off = 16; off; off >>= 1) {
                float v2 = __shfl_down_sync(0xffffffffu, bv0, off);
                int   i2 = __shfl_down_sync(0xffffffffu, bi0, off);
                if (v2 > bv0 || (v2 == bv0 && i2 < bi0)) { bv0 = v2; bi0 = i2; }
            }
            if (0.0f > bv0 || (0.0f == bv0 && 30 < bi0)) bi0 = 30;  // first zero = 30
            if (lane == 0) s_argm[s][0] = bi0;
        }

        // levels 1..3 with compile-time bounds; (lo+2)*4 is 16B-aligned for all
        const int LO[3]  = {30, 430, 3430};
        const int NV4[3] = {99, 749, 2499};   // (len-2)/4; head 2 + tail 2 floats
#pragma unroll
        for (int k = 0; k < 3; k++) {
            const int lo = LO[k];
            const int nv = NV4[k];
            float mbv = -3.4e38f; int mbi = C_TOTAL; float mss = 0.0f;

            if (tid < 2) {                         // head pair
                float v = row[lo + tid];
                if (v > mbv) { mbv = v; mbi = lo + tid; }
                mss += fexp(v);
            }
            const float4* pv = (const float4*)(row + lo + 2);
#pragma unroll 4
            for (int j = tid; j < nv; j += NT) {
                float4 q = pv[j];
                int b0 = lo + 2 + 4 * j;
                if (q.x > mbv) { mbv = q.x; mbi = b0;     }
                if (q.y > mbv) { mbv = q.y; mbi = b0 + 1; }
                if (q.z > mbv) { mbv = q.z; mbi = b0 + 2; }
                if (q.w > mbv) { mbv = q.w; mbi = b0 + 3; }
                mss += (fexp(q.x) + fexp(q.y)) + (fexp(q.z) + fexp(q.w));
            }
            if (tid < 2) {                         // tail pair
                int idx = lo + 2 + 4 * nv + tid;
                float v = row[idx];
                if (v > mbv) { mbv = v; mbi = idx; }
                mss += fexp(v);
            }
            // warp reduce (lexicographic max + sum)
#pragma unroll
            for (int off = 16; off; off >>= 1) {
                float v2 = __shfl_down_sync(0xffffffffu, mbv, off);
                int   i2 = __shfl_down_sync(0xffffffffu, mbi, off);
                mss     += __shfl_down_sync(0xffffffffu, mss, off);
                if (v2 > mbv || (v2 == mbv && i2 < mbi)) { mbv = v2; mbi = i2; }
            }
            if (lane == 0) { s_v[k][wid] = mbv; s_i[k][wid] = mbi; s_s[k][wid] = mss; }
        }
        __syncthreads();

        // thread 0: combine warps, stash per-sample meta (no H access here)
        if (tid == 0) {
            const int LEN[3] = {400, 3000, 10000};
#pragma unroll
            for (int k = 0; k < 3; k++) {
                float v = s_v[k][0]; int ix = s_i[k][0]; float sm = s_s[k][0];
#pragma unroll
                for (int w = 1; w < NW; w++) {
                    float v2 = s_v[k][w]; int i2 = s_i[k][w];
                    sm += s_s[k][w];
                    if (v2 > v || (v2 == v && i2 < ix)) { v = v2; ix = i2; }
                }
                if (0.0f > v || (0.0f == v && 0 < ix)) ix = 0;  // first zero = idx 0
                s_argm[s][k + 1] = ix;
                s_S[s][k] = sm + (float)(C_TOTAL - LEN[k]); // exp(0)=1 out-of-level
                int t = yt[(bid * SPC + s) * 4 + (k + 1)];
                s_rowt[s][k] = row[t];
            }
        }
        __syncthreads();   // meta done; buffer (s&1) may be overwritten next iter
    }

    // ---- parallel per-sample epilogue: threads 0..SPC-1, one sample each
    if (tid < SPC) {
        const int i = bid * SPC + tid;
        const float W[3] = {0.25f, 0.15f, 0.10f};
        const float E = 2.718281828459045f;
        float acc = 0.0f;
        int argmPrev = s_argm[tid][0];
#pragma unroll
        for (int k = 0; k < 3; k++) {
            int ix = s_argm[tid][k + 1];
            float term = (__logf(s_S[tid][k]) - s_rowt[tid][k]) * (1.0f / (float)N_SAMPLES);
            if (i > 0) {
                float h = __ldg(&H[(size_t)argmPrev * C_TOTAL + ix]);
                if (h == 0.0f) term += E;
            }
            acc += W[k] * term;
            argmPrev = ix;
        }
        g_partial[i] = acc;
        __threadfence();
        unsigned t = atomicAdd(&g_ticket, 1u);
        if (t == N_SAMPLES - 1) s_last = 1;
    }
    __syncthreads();

    // ---- last ticket holder's block: fixed-order deterministic sum
    if (s_last) {
        __threadfence();  // acquire all g_partial stores
        float4 q = ((const float4*)g_partial)[tid];   // 256 threads x 4 = 1024
        float sm = (q.x + q.y) + (q.z + q.w);
#pragma unroll
        for (int off = 16; off; off >>= 1)
            sm += __shfl_down_sync(0xffffffffu, sm, off);
        __shared__ float red[NW];
        if (lane == 0) red[wid] = sm;
        __syncthreads();
        if (tid == 0) {
            float tot = 0.0f;
#pragma unroll
            for (int w = 0; w < NW; w++) tot += red[w];
            out[0] = tot;
            g_ticket = 0;   // reset for next graph replay
        }
    }
}

extern "C" void kernel_launch(void* const* d_in, const int* in_sizes, int n_in,
                              void* d_out, int out_size)
{
    const float* yp = (const float*)d_in[0];   // [1024, 13430] f32
    const int*   yt = (const int*)d_in[1];     // [1024, 4] i32
    const float* H  = (const float*)d_in[2];   // [13430, 13430] f32
    float* out = (float*)d_out;

    const int dyn = 2 * BUF_F * sizeof(float);  // 107,520 B
    cudaFuncSetAttribute(taxa_kernel, cudaFuncAttributeMaxDynamicSharedMemorySize, dyn);
    taxa_kernel<<<GRID, NT, dyn>>>(yp, yt, H, out);
}

// round 6
// speedup vs baseline: 1.3928x; 1.3928x over previous
#include <cuda_runtime.h>
#include <cstdint>

// TaxaNetLoss: loss = sum_{k=1..3} W[k] * (viol_k * e + ce_k)
//   viol_k = #{ i in [1,N) : H[argm[k-1,i], argm[k,i]] == 0 }
//   ce_k   = mean_i ( log( sum_{j in lvl k} exp(yp[i,j]) + (C - L_k) ) - yp[i, yt[i,k]] )
//   argm[k,i] = argmax of yp masked to level k (zeros outside), first-occurrence
//               tie-break -> implicit zero candidate at first out-of-level index
//               (30 for k=0, 0 for k>=1).
// One 128-thread CTA per sample (whole grid resident in a single wave).
// Epilogue (warp-combine, CE, H gather) is parallelized across lanes 0..2 of
// warp 0 so the 3 H loads overlap. Last ticket holder sums the 1024 partials
// in fixed order (bit-deterministic) and resets the ticket (graph-replay safe).

#define N_SAMPLES 1024
#define C_TOTAL   13430
#define NT        128
#define NW        (NT / 32)

static __device__ __align__(16) float g_partial[N_SAMPLES];
static __device__ unsigned int g_ticket = 0;

__device__ __forceinline__ float fexp(float x) {
    // Schraudolph fast exp: 1 FFMA + 1 F2I, ~+-3% rel err; lse error ~1e-5 rel on loss.
    return __int_as_float((int)fmaf(x, 12102203.0f, 1064866805.0f));
}

__global__ __launch_bounds__(NT) void taxa_kernel(
    const float* __restrict__ yp, const int* __restrict__ yt,
    const float* __restrict__ H, float* __restrict__ out)
{
    const int i    = blockIdx.x;       // sample
    const int tid  = threadIdx.x;
    const int lane = tid & 31;
    const int wid  = tid >> 5;
    const float* row = yp + (size_t)i * C_TOTAL;

    __shared__ float s_v[3][NW];
    __shared__ int   s_i[3][NW];
    __shared__ float s_s[3][NW];
    __shared__ int   s_am[4];      // argm[0..3]
    __shared__ float s_term[3];
    __shared__ int   s_last;

    if (tid == 0) s_last = 0;

    // ---- level 0 (30 elems): warp 0
    if (wid == 0) {
        float bv0 = (lane < 30) ? row[lane] : -3.4e38f;
        int   bi0 = (lane < 30) ? lane : C_TOTAL;
#pragma unroll
        for (int off = 16; off; off >>= 1) {
            float v2 = __shfl_down_sync(0xffffffffu, bv0, off);
            int   i2 = __shfl_down_sync(0xffffffffu, bi0, off);
            if (v2 > bv0 || (v2 == bv0 && i2 < bi0)) { bv0 = v2; bi0 = i2; }
        }
        if (0.0f > bv0 || (0.0f == bv0 && 30 < bi0)) bi0 = 30;  // first zero = 30
        if (lane == 0) s_am[0] = bi0;
    }

    // ---- levels 1..3: streaming argmax + sum-of-exp, warp-reduced
    const int LO[4] = {30, 430, 3430, 13430};
#pragma unroll
    for (int k = 0; k < 3; k++) {
        const int lo  = LO[k];
        const int len = LO[k + 1] - lo;
        float mbv = -3.4e38f; int mbi = C_TOTAL; float mss = 0.0f;

        const float* p = row + lo;
        int head = (int)(((16u - ((uintptr_t)p & 15u)) & 15u) >> 2);  // 0 or 2 here

        for (int j = tid; j < head; j += NT) {
            float v = p[j];
            if (v > mbv) { mbv = v; mbi = lo + j; }
            mss += fexp(v);
        }
        const int nv = (len - head) >> 2;
        const float4* pv = (const float4*)(p + head);
#pragma unroll 4
        for (int j = tid; j < nv; j += NT) {
            float4 q = pv[j];
            int b0 = lo + head + 4 * j;
            if (q.x > mbv) { mbv = q.x; mbi = b0;     }
            if (q.y > mbv) { mbv = q.y; mbi = b0 + 1; }
            if (q.z > mbv) { mbv = q.z; mbi = b0 + 2; }
            if (q.w > mbv) { mbv = q.w; mbi = b0 + 3; }
            mss += (fexp(q.x) + fexp(q.y)) + (fexp(q.z) + fexp(q.w));
        }
        for (int j = head + 4 * nv + tid; j < len; j += NT) {
            float v = p[j];
            if (v > mbv) { mbv = v; mbi = lo + j; }
            mss += fexp(v);
        }
        // warp reduce (lexicographic max + sum)
#pragma unroll
        for (int off = 16; off; off >>= 1) {
            float v2 = __shfl_down_sync(0xffffffffu, mbv, off);
            int   i2 = __shfl_down_sync(0xffffffffu, mbi, off);
            mss     += __shfl_down_sync(0xffffffffu, mss, off);
            if (v2 > mbv || (v2 == mbv && i2 < mbi)) { mbv = v2; mbi = i2; }
        }
        if (lane == 0) { s_v[k][wid] = mbv; s_i[k][wid] = mbi; s_s[k][wid] = mss; }
    }
    __syncthreads();

    // ---- epilogue on warp 0: lane k (k<3) handles level k+1 independently
    if (wid == 0) {
        float S = 0.0f; float rowt = 0.0f;
        if (lane < 3) {
            const int k = lane;
            const int LEN[3] = {400, 3000, 10000};
            float v = s_v[k][0]; int ix = s_i[k][0]; float sm = s_s[k][0];
#pragma unroll
            for (int w = 1; w < NW; w++) {
                float v2 = s_v[k][w]; int i2 = s_i[k][w];
                sm += s_s[k][w];
                if (v2 > v || (v2 == v && i2 < ix)) { v = v2; ix = i2; }
            }
            if (0.0f > v || (0.0f == v && 0 < ix)) ix = 0;  // first zero = idx 0
            s_am[k + 1] = ix;
            S = sm + (float)(C_TOTAL - LEN[k]);              // exp(0)=1 outside level
            int t = __ldg(&yt[i * 4 + (k + 1)]);
            rowt = __ldg(&row[t]);                           // parallel gather
        }
        __syncwarp();
        if (lane < 3) {
            const int k = lane;
            const float E = 2.718281828459045f;
            float term = (__logf(S) - rowt) * (1.0f / (float)N_SAMPLES);
            if (i > 0) {
                int a = s_am[k], b = s_am[k + 1];
                float h = __ldg(&H[(size_t)a * C_TOTAL + b]);  // 3 lanes: parallel
                if (h == 0.0f) term += E;
            }
            s_term[k] = term;
        }
        __syncwarp();
        if (lane == 0) {
            g_partial[i] = 0.25f * s_term[0] + 0.15f * s_term[1] + 0.10f * s_term[2];
            __threadfence();
            unsigned t = atomicAdd(&g_ticket, 1u);
            if (t == N_SAMPLES - 1) s_last = 1;
        }
    }
    __syncthreads();

    // ---- last ticket holder's block: fixed-order deterministic sum
    if (s_last) {
        __threadfence();  // acquire all g_partial stores
        const float4* p4 = (const float4*)g_partial;
        float4 a = p4[tid];           // 128 threads x 8 floats = 1024
        float4 b = p4[tid + NT];
        float sm = ((a.x + a.y) + (a.z + a.w)) + ((b.x + b.y) + (b.z + b.w));
#pragma unroll
        for (int off = 16; off; off >>= 1)
            sm += __shfl_down_sync(0xffffffffu, sm, off);
        __shared__ float red[NW];
        if (lane == 0) red[wid] = sm;
        __syncthreads();
        if (tid == 0) {
            float tot = 0.0f;
#pragma unroll
            for (int w = 0; w < NW; w++) tot += red[w];
            out[0] = tot;
            g_ticket = 0;   // reset for next graph replay
        }
    }
}

extern "C" void kernel_launch(void* const* d_in, const int* in_sizes, int n_in,
                              void* d_out, int out_size)
{
    const float* yp = (const float*)d_in[0];   // [1024, 13430] f32
    const int*   yt = (const int*)d_in[1];     // [1024, 4] i32
    const float* H  = (const float*)d_in[2];   // [13430, 13430] f32
    float* out = (float*)d_out;

    taxa_kernel<<<N_SAMPLES, NT>>>(yp, yt, H, out);
}